// round 12
// baseline (speedup 1.0000x reference)
#include <cuda_runtime.h>
#include <cuda_bf16.h>
#include <cuda_fp16.h>
#include <cstdint>

#define Bsz  512
#define Tlen 128
#define Idim 512
#define Hdim 512
#define Cnum 97
#define Snum 26
#define ICdim 609
#define KC  32                      // K elements per stage
#define KCP 40                      // padded row (80 B) -> conflict-free LDSM

#define GDC_WAIT   asm volatile("griddepcontrol.wait;" ::: "memory")
#define GDC_LAUNCH asm volatile("griddepcontrol.launch_dependents;" ::: "memory")

// ---------------- device scratch (allocation-free rule) ----------------
__device__ __align__(16) __half g_feat16[(size_t)Bsz * Tlen * Hdim];  // 64 MiB
__device__ __align__(16) __half g_bh16[(size_t)Bsz * Tlen * Idim];    // 64 MiB
__device__ __align__(16) __nv_bfloat16 g_bhHi[(size_t)Bsz * Tlen * Idim];
__device__ __align__(16) __nv_bfloat16 g_bhLo[(size_t)Bsz * Tlen * Idim];
__device__ __align__(16) __nv_bfloat16 g_xhHi[2][Bsz * 1024];  // ping-pong [ctx|h]
__device__ __align__(16) __nv_bfloat16 g_xhLo[2][Bsz * 1024];
__device__ __align__(16) __nv_bfloat16 g_outhHi[(size_t)Bsz * Snum * Hdim];
__device__ __align__(16) __nv_bfloat16 g_outhLo[(size_t)Bsz * Snum * Hdim];
__device__ __align__(16) float g_hp[Bsz * Hdim];
__device__ __align__(16) float g_c[Bsz * Hdim];
__device__ __align__(16) float g_b2i[2048];                 // interleaved bias
__device__ __align__(16) float g_Wembi[Cnum * 2048];        // interleaved emb
// pre-split bf16 weights (hi/lo), [N,K] row-major
__device__ __align__(16) __nv_bfloat16 g_W2hi[2048 * 1024]; // interleaved rows
__device__ __align__(16) __nv_bfloat16 g_W2lo[2048 * 1024];
__device__ __align__(16) __nv_bfloat16 g_Wfhi[512 * 512];
__device__ __align__(16) __nv_bfloat16 g_Wflo[512 * 512];
__device__ __align__(16) __nv_bfloat16 g_Whhi[512 * 512];
__device__ __align__(16) __nv_bfloat16 g_Whlo[512 * 512];
__device__ __align__(16) __nv_bfloat16 g_Wghi[Cnum * 512];
__device__ __align__(16) __nv_bfloat16 g_Wglo[Cnum * 512];

// ---------------- helpers ----------------
__device__ __forceinline__ void stC(float* p, float v)  { *p = v; }
__device__ __forceinline__ void stC(__half* p, float v) { *p = __float2half(v); }

__device__ __forceinline__ float tanh_fast(float x) {
    float y;
    asm("tanh.approx.f32 %0, %1;" : "=f"(y) : "f"(x));
    return y;
}

__device__ __forceinline__ void split1(float v, __nv_bfloat16* hi, __nv_bfloat16* lo) {
    __nv_bfloat16 h = __float2bfloat16(v);
    *hi = h;
    *lo = __float2bfloat16(v - __bfloat162float(h));
}

#define MMA_B16(d, a, b)                                                     \
    asm volatile(                                                            \
        "mma.sync.aligned.m16n8k16.row.col.f32.bf16.bf16.f32 "               \
        "{%0,%1,%2,%3},{%4,%5,%6,%7},{%8,%9},{%0,%1,%2,%3};"                 \
        : "+f"((d)[0]), "+f"((d)[1]), "+f"((d)[2]), "+f"((d)[3])             \
        : "r"((a)[0]), "r"((a)[1]), "r"((a)[2]), "r"((a)[3]),                \
          "r"((b)[0]), "r"((b)[1]))

#define LDSM_X4(r, addr)                                                     \
    asm volatile("ldmatrix.sync.aligned.m8n8.x4.shared.b16 {%0,%1,%2,%3},[%4];" \
        : "=r"((r)[0]), "=r"((r)[1]), "=r"((r)[2]), "=r"((r)[3]) : "r"(addr))

#define CP16(dst, src, sz)                                                   \
    asm volatile("cp.async.cg.shared.global [%0], [%1], 16, %2;\n"           \
                 :: "r"(dst), "l"(src), "r"(sz))

// ====== templated pipeline: acc += A*B^T over K, double-buffered cp.async ====
// PDL==2: B-chunk0 prefetch pre-wait (B must be >= 2 kernels old), then
// griddepcontrol wait + launch_dependents, then A-chunk0.
// Per-output accumulation order identical for all configs -> bit-identical.
template<int BM, int BN, int WR, int PDL, int MT, int NT>
__device__ __forceinline__ void gemm_pipe(
    float (&acc)[MT][NT][4],
    const __nv_bfloat16* __restrict__ Ahi, const __nv_bfloat16* __restrict__ Alo,
    int lda,
    const __nv_bfloat16* __restrict__ Bhi, const __nv_bfloat16* __restrict__ Blo,
    int ldb, int N, int K, int m0, int n0, char* smem)
{
    constexpr int WC = 8 / WR;
    constexpr int ASTG = BM * KCP * 2;
    constexpr int BSTG = BN * KCP * 2;
    constexpr int STGT = 2 * (ASTG + BSTG);
    static_assert(MT == BM / (16 * WR) && NT == BN / (8 * WC), "tile mismatch");

    const uint32_t sbase = (uint32_t)__cvta_generic_to_shared(smem);
    const int tid = threadIdx.x, lane = tid & 31, warp = tid >> 5;
    const int wm = (warp / WC) * (MT * 16);
    const int wn = (warp % WC) * (NT * 8);

    const uint32_t aOff = (uint32_t)((wm + (lane & 15)) * (KCP * 2) + (lane >> 4) * 16);
    const uint32_t bOff = (uint32_t)((wn + ((lane >> 4) << 3) + (lane & 7)) * (KCP * 2)
                                     + ((lane >> 3) & 1) * 16);

    const __nv_bfloat16* asrc[2] = { Ahi, Alo };
    const __nv_bfloat16* bsrc[2] = { Bhi, Blo };

    auto pfA = [&](int stg, int k0) {
        uint32_t st = sbase + (uint32_t)(stg * STGT);
#pragma unroll
        for (int ch = tid; ch < BM * 4; ch += 256) {
            int row = ch >> 2, cc = ch & 3;
#pragma unroll
            for (int t = 0; t < 2; t++) {
                const void* sa = asrc[t] + (size_t)(m0 + row) * lda + k0 + cc * 8;
                uint32_t da = st + (uint32_t)(t * ASTG + row * (KCP * 2) + cc * 16);
                CP16(da, sa, 16);
            }
        }
    };
    auto pfB = [&](int stg, int k0) {
        uint32_t st = sbase + (uint32_t)(stg * STGT);
#pragma unroll
        for (int ch = tid; ch < BN * 4; ch += 256) {
            int row = ch >> 2, cc = ch & 3;
            int gr = n0 + row;
            int rr = (gr < N) ? gr : 0;
            int sz = (gr < N) ? 16 : 0;
#pragma unroll
            for (int t = 0; t < 2; t++) {
                const void* sb = bsrc[t] + (size_t)rr * ldb + k0 + cc * 8;
                uint32_t db = st + (uint32_t)(2 * ASTG + t * BSTG + row * (KCP * 2) + cc * 16);
                CP16(db, sb, sz);
            }
        }
    };

    if (PDL == 2) {
        pfB(0, 0);
        GDC_WAIT;
        GDC_LAUNCH;
        pfA(0, 0);
    } else {
        pfB(0, 0);
        pfA(0, 0);
    }
    asm volatile("cp.async.commit_group;\n");

    const int nch = K / KC;
    for (int kc = 0; kc < nch; kc++) {
        if (kc + 1 < nch) {
            pfB((kc + 1) & 1, (kc + 1) * KC);
            pfA((kc + 1) & 1, (kc + 1) * KC);
            asm volatile("cp.async.commit_group;\n");
            asm volatile("cp.async.wait_group 1;\n");
        } else {
            asm volatile("cp.async.wait_group 0;\n");
        }
        __syncthreads();

        uint32_t st = sbase + (uint32_t)((kc & 1) * STGT);
        uint32_t aB[2] = { st, st + ASTG };
        uint32_t bB[2] = { st + 2 * ASTG, st + 2 * ASTG + BSTG };

#pragma unroll
        for (int k16 = 0; k16 < 2; k16++) {
            uint32_t af[2][MT][4];
#pragma unroll
            for (int t = 0; t < 2; t++)
#pragma unroll
                for (int mt = 0; mt < MT; mt++) {
                    uint32_t ad = aB[t] + aOff + (uint32_t)(mt * 16 * KCP * 2 + k16 * 32);
                    LDSM_X4(af[t][mt], ad);
                }
#pragma unroll
            for (int p = 0; p < NT / 2; p++) {
                uint32_t bf[2][2][2];
#pragma unroll
                for (int t = 0; t < 2; t++) {
                    uint32_t bd = bB[t] + bOff + (uint32_t)(p * 16 * KCP * 2 + k16 * 32);
                    uint32_t r4[4];
                    LDSM_X4(r4, bd);
                    bf[t][0][0] = r4[0]; bf[t][0][1] = r4[1];
                    bf[t][1][0] = r4[2]; bf[t][1][1] = r4[3];
                }
#pragma unroll
                for (int mt = 0; mt < MT; mt++)
#pragma unroll
                    for (int q = 0; q < 2; q++) {
                        int nt = 2 * p + q;
                        MMA_B16(acc[mt][nt], af[0][mt], bf[0][q]);  // hi*hi
                        MMA_B16(acc[mt][nt], af[0][mt], bf[1][q]);  // hi*lo
                        MMA_B16(acc[mt][nt], af[1][mt], bf[0][q]);  // lo*hi
                    }
            }
        }
        __syncthreads();
    }
}

// ---------------- generic GEMM kernel (feat / hp / final) ----------------
// PDLMODE: 0 none, 1 wait-first (A and B both freshly produced), 2 B-prefetch pre-wait
template<int BM, int BN, int WR, int PDLMODE, int BIAS, typename OutT>
__global__ void __launch_bounds__(256, 2) gemm2(
    const __nv_bfloat16* __restrict__ Ahi, const __nv_bfloat16* __restrict__ Alo,
    int lda,
    const __nv_bfloat16* __restrict__ Bhi, const __nv_bfloat16* __restrict__ Blo,
    int ldb,
    OutT* __restrict__ C, int ldc, const float* __restrict__ bias,
    int N, int K)
{
    extern __shared__ __align__(16) char smem[];
    constexpr int WC = 8 / WR;
    constexpr int MT = BM / (16 * WR);
    constexpr int NT = BN / (8 * WC);
    const int m0 = blockIdx.y * BM, n0 = blockIdx.x * BN;
    const int lane = threadIdx.x & 31, warp = threadIdx.x >> 5;
    const int wm = (warp / WC) * (MT * 16);
    const int wn = (warp % WC) * (NT * 8);

    if (PDLMODE == 1) { GDC_WAIT; GDC_LAUNCH; }

    float acc[MT][NT][4];
#pragma unroll
    for (int i = 0; i < MT; i++)
#pragma unroll
        for (int j = 0; j < NT; j++)
#pragma unroll
            for (int r = 0; r < 4; r++) acc[i][j][r] = 0.f;

    gemm_pipe<BM, BN, WR, (PDLMODE == 2) ? 2 : 0>(
        acc, Ahi, Alo, lda, Bhi, Blo, ldb, N, K, m0, n0, smem);

    const int gid = lane >> 2, tig = lane & 3;
#pragma unroll
    for (int mt = 0; mt < MT; mt++) {
        int r0 = m0 + wm + mt * 16 + gid;
#pragma unroll
        for (int nt = 0; nt < NT; nt++) {
            int col = n0 + wn + nt * 8 + 2 * tig;
            float b0 = 0.f, b1 = 0.f;
            if (BIAS) {
                if (col < N)     b0 = bias[col];
                if (col + 1 < N) b1 = bias[col + 1];
            }
            if (col < N) {
                stC(&C[(size_t)r0 * ldc + col],       acc[mt][nt][0] + b0);
                stC(&C[(size_t)(r0 + 8) * ldc + col], acc[mt][nt][2] + b0);
            }
            if (col + 1 < N) {
                stC(&C[(size_t)r0 * ldc + col + 1],       acc[mt][nt][1] + b1);
                stC(&C[(size_t)(r0 + 8) * ldc + col + 1], acc[mt][nt][3] + b1);
            }
        }
    }
}

// ---------------- fused gates GEMM + LSTM epilogue ----------------
// BM=128, BN=64, WR=4 -> warp tile 32x32, grid (32, 4) = 128 blocks.
__global__ void __launch_bounds__(256, 2) gates_lstm_kernel(
    const __nv_bfloat16* __restrict__ Ahi, const __nv_bfloat16* __restrict__ Alo,
    __nv_bfloat16* __restrict__ xhHiN, __nv_bfloat16* __restrict__ xhLoN,
    const float* __restrict__ b2i, const float* __restrict__ Wembi,
    const int* __restrict__ text, int s, float* __restrict__ c,
    __nv_bfloat16* __restrict__ outhHi, __nv_bfloat16* __restrict__ outhLo)
{
    extern __shared__ __align__(16) char smem[];
    constexpr int BM = 128, BN = 64, WR = 4, WC = 2;
    constexpr int MT = BM / (16 * WR);   // 2
    constexpr int NT = BN / (8 * WC);    // 4
    const int tid = threadIdx.x, lane = tid & 31, warp = tid >> 5;
    const int wm = (warp / WC) * (MT * 16);
    const int wn = (warp % WC) * (NT * 8);
    const int m0 = blockIdx.y * BM, n0 = blockIdx.x * BN, j0 = n0 >> 2;

    float acc[MT][NT][4];
#pragma unroll
    for (int i = 0; i < MT; i++)
#pragma unroll
        for (int j = 0; j < NT; j++)
#pragma unroll
            for (int r = 0; r < 4; r++) acc[i][j][r] = 0.f;

    // PDL=2: W2 chunk-0 prefetch overlaps attn tail; wait before reading xh
    gemm_pipe<BM, BN, WR, 2>(acc, Ahi, Alo, 1024, g_W2hi, g_W2lo, 1024,
                             2048, 1024, m0, n0, smem);

    // dump acc to smem (raw gate pre-activations for this 128x64 region)
    float* sg = (float*)smem;
    const int gid = lane >> 2, tig = lane & 3;
#pragma unroll
    for (int mt = 0; mt < MT; mt++) {
        int rl = wm + mt * 16 + gid;
#pragma unroll
        for (int nt = 0; nt < NT; nt++) {
            int cl = wn + nt * 8 + 2 * tig;
            sg[rl * BN + cl]           = acc[mt][nt][0];
            sg[rl * BN + cl + 1]       = acc[mt][nt][1];
            sg[(rl + 8) * BN + cl]     = acc[mt][nt][2];
            sg[(rl + 8) * BN + cl + 1] = acc[mt][nt][3];
        }
    }
    __syncthreads();

    // LSTM for (128 batches x 16 j): 2048 tasks, 8 per thread
#pragma unroll
    for (int it = 0; it < 8; it++) {
        int idx = tid + it * 256;
        int bl = idx >> 4, jl = idx & 15;
        int b = m0 + bl, j = j0 + jl;
        int ch = text[b * Snum + s];
        float4 gv = *reinterpret_cast<float4*>(&sg[bl * BN + jl * 4]);
        float4 bs = *reinterpret_cast<const float4*>(&b2i[n0 + jl * 4]);
        float4 ev = *reinterpret_cast<const float4*>(&Wembi[(size_t)ch * 2048 + n0 + jl * 4]);
        float ig = gv.x + bs.x + ev.x;
        float fg = gv.y + bs.y + ev.y;
        float gg = gv.z + bs.z + ev.z;
        float og = gv.w + bs.w + ev.w;
        float si = 1.f / (1.f + __expf(-ig));
        float sf = 1.f / (1.f + __expf(-fg));
        float so = 1.f / (1.f + __expf(-og));
        float c2v = sf * c[b * 512 + j] + si * tanhf(gg);
        float h2 = so * tanhf(c2v);
        c[b * 512 + j] = c2v;
        __nv_bfloat16 hh, hl;
        split1(h2, &hh, &hl);
        xhHiN[(size_t)b * 1024 + 512 + j] = hh;
        xhLoN[(size_t)b * 1024 + 512 + j] = hl;
        size_t oi = ((size_t)b * Snum + s) * 512 + j;
        outhHi[oi] = hh;
        outhLo[oi] = hl;
    }
}

// ---------------- mega pack: all one-time packs + init in ONE kernel ---------
#define NB_BH   32768   // (B*T*I/4)/256
#define NB_W2   8192    // 2048*1024/256
#define NB_WF   1024
#define NB_WH   1024
#define NB_WG   194
#define NB_EMB  776
#define NB_INIT 2048
#define NB_TOTAL (NB_BH + NB_W2 + NB_WF + NB_WH + NB_WG + NB_EMB + NB_INIT)

__global__ void __launch_bounds__(256) mega_pack_kernel(
    const float* __restrict__ bh, const float* __restrict__ W_feat,
    const float* __restrict__ W_hid, const float* __restrict__ b_hid,
    const float* __restrict__ W_ih, const float* __restrict__ W_hh,
    const float* __restrict__ b_ih, const float* __restrict__ b_hh,
    const float* __restrict__ W_gen)
{
    GDC_LAUNCH;
    int bid = blockIdx.x, tid = threadIdx.x;

    if (bid < NB_BH) {        // batch_H -> fp16 + bf16 hi/lo
        int i = bid * 256 + tid;
        float4 v = reinterpret_cast<const float4*>(bh)[i];
        reinterpret_cast<__half2*>(g_bh16)[2 * i]     = __floats2half2_rn(v.x, v.y);
        reinterpret_cast<__half2*>(g_bh16)[2 * i + 1] = __floats2half2_rn(v.z, v.w);
        __nv_bfloat16 h0, l0, h1, l1, h2, l2, h3, l3;
        split1(v.x, &h0, &l0); split1(v.y, &h1, &l1);
        split1(v.z, &h2, &l2); split1(v.w, &h3, &l3);
        __nv_bfloat162* ph = reinterpret_cast<__nv_bfloat162*>(g_bhHi);
        __nv_bfloat162* pl = reinterpret_cast<__nv_bfloat162*>(g_bhLo);
        ph[2 * i]     = __nv_bfloat162(h0, h1);
        ph[2 * i + 1] = __nv_bfloat162(h2, h3);
        pl[2 * i]     = __nv_bfloat162(l0, l1);
        pl[2 * i + 1] = __nv_bfloat162(l2, l3);
        return;
    }
    bid -= NB_BH;
    if (bid < NB_W2) {        // W2 interleaved split + bias
        int i = bid * 256 + tid;
        int n = i >> 10, k = i & 1023;
        int r = (n & 3) * 512 + (n >> 2);
        float v = (k < 512) ? W_ih[(size_t)r * ICdim + k]
                            : W_hh[(size_t)r * 512 + (k - 512)];
        split1(v, &g_W2hi[i], &g_W2lo[i]);
        if (i < 2048) {
            int rr = (i & 3) * 512 + (i >> 2);
            g_b2i[i] = b_ih[rr] + b_hh[rr];
        }
        return;
    }
    bid -= NB_W2;
    if (bid < NB_WF) {        // W_feat split
        int i = bid * 256 + tid;
        split1(W_feat[i], &g_Wfhi[i], &g_Wflo[i]);
        return;
    }
    bid -= NB_WF;
    if (bid < NB_WH) {        // W_hid split
        int i = bid * 256 + tid;
        split1(W_hid[i], &g_Whhi[i], &g_Whlo[i]);
        return;
    }
    bid -= NB_WH;
    if (bid < NB_WG) {        // W_gen split
        int i = bid * 256 + tid;
        if (i < Cnum * 512) split1(W_gen[i], &g_Wghi[i], &g_Wglo[i]);
        return;
    }
    bid -= NB_WG;
    if (bid < NB_EMB) {       // onehot embedding (interleaved)
        int i = bid * 256 + tid;
        if (i < Cnum * 2048) {
            int cc = i >> 11, n = i & 2047;
            int r = (n & 3) * 512 + (n >> 2);
            g_Wembi[i] = W_ih[(size_t)r * ICdim + 512 + cc];
        }
        return;
    }
    bid -= NB_EMB;
    {                          // init xh / c / hp0
        int i = bid * 256 + tid;
        __nv_bfloat16 z = __float2bfloat16(0.f);
        g_xhHi[0][i] = z; g_xhLo[0][i] = z;
        g_xhHi[1][i] = z; g_xhLo[1][i] = z;
        if (i < Bsz * Hdim) {
            g_c[i] = 0.f;
            g_hp[i] = b_hid[i & 511];         // h0 = 0 -> hp0 = b_hid
        }
    }
}

// ---------------- fused attention: e -> softmax -> ctx -----------------------
__global__ void __launch_bounds__(256) attn_kernel(
    const __half* __restrict__ feat,
    const __half* __restrict__ bh,
    const float* __restrict__ hp,
    const float* __restrict__ wsc,
    __nv_bfloat16* __restrict__ xhHi, __nv_bfloat16* __restrict__ xhLo)
{
    int b = blockIdx.x, tid = threadIdx.x;
    int warp = tid >> 5, lane = tid & 31;
    __shared__ float s_al[Tlen];
    __shared__ float s_red[8];
    __shared__ float s_ctx[4][512];

    // pre-wait: w_score (harness input, always stable)
    float wr[16];
#pragma unroll
    for (int j = 0; j < 2; j++) {
        float4 w0 = *reinterpret_cast<const float4*>(wsc + j * 256 + lane * 8);
        float4 w1 = *reinterpret_cast<const float4*>(wsc + j * 256 + lane * 8 + 4);
        wr[j*8+0]=w0.x; wr[j*8+1]=w0.y; wr[j*8+2]=w0.z; wr[j*8+3]=w0.w;
        wr[j*8+4]=w1.x; wr[j*8+5]=w1.y; wr[j*8+6]=w1.z; wr[j*8+7]=w1.w;
    }

    GDC_WAIT;      // hp (from hp-GEMM) must be complete
    GDC_LAUNCH;    // let gates_lstm start its weight prefetch

    float hpr[16];
    {
        const float* hpb = hp + (size_t)b * 512;
#pragma unroll
        for (int j = 0; j < 2; j++) {
            float4 a0 = *reinterpret_cast<const float4*>(hpb + j * 256 + lane * 8);
            float4 a1 = *reinterpret_cast<const float4*>(hpb + j * 256 + lane * 8 + 4);
            hpr[j*8+0]=a0.x; hpr[j*8+1]=a0.y; hpr[j*8+2]=a0.z; hpr[j*8+3]=a0.w;
            hpr[j*8+4]=a1.x; hpr[j*8+5]=a1.y; hpr[j*8+6]=a1.z; hpr[j*8+7]=a1.w;
        }
    }

    // e-pass: warp per t, 16 t per warp, 16B feat loads
    for (int t = warp; t < Tlen; t += 8) {
        const uint4* f4 = reinterpret_cast<const uint4*>(
            feat + ((size_t)b * Tlen + t) * Hdim);
        float s = 0.f;
#pragma unroll
        for (int j = 0; j < 2; j++) {
            uint4 v = f4[lane + 32 * j];
            const __half2* hx = reinterpret_cast<const __half2*>(&v);
#pragma unroll
            for (int q = 0; q < 4; q++) {
                float2 f = __half22float2(hx[q]);
                s += tanh_fast(f.x + hpr[j*8 + 2*q])     * wr[j*8 + 2*q]
                   + tanh_fast(f.y + hpr[j*8 + 2*q + 1]) * wr[j*8 + 2*q + 1];
            }
        }
#pragma unroll
        for (int o = 16; o; o >>= 1) s += __shfl_down_sync(0xffffffffu, s, o);
        if (lane == 0) s_al[t] = s;
    }
    __syncthreads();

    // softmax (threads 0..127)
    if (tid < Tlen) {
        float v = s_al[tid];
        float m = v;
#pragma unroll
        for (int o = 16; o; o >>= 1) m = fmaxf(m, __shfl_xor_sync(0xffffffffu, m, o));
        if (lane == 0) s_red[warp] = m;
    }
    __syncthreads();
    if (tid < Tlen) {
        float m = fmaxf(fmaxf(s_red[0], s_red[1]), fmaxf(s_red[2], s_red[3]));
        float ex = __expf(s_al[tid] - m);
        float ss = ex;
#pragma unroll
        for (int o = 16; o; o >>= 1) ss += __shfl_xor_sync(0xffffffffu, ss, o);
        if (lane == 0) s_red[4 + warp] = ss;
        s_al[tid] = ex;
    }
    __syncthreads();
    if (tid < Tlen) {
        float inv = 1.f / (s_red[4] + s_red[5] + s_red[6] + s_red[7]);
        s_al[tid] *= inv;
    }
    __syncthreads();

    // ctx-pass: 4 T-groups x 64 threads; each thread owns 8 cols, 16B loads
    {
        int g = tid >> 6, l = tid & 63;
        float acc[8];
#pragma unroll
        for (int q = 0; q < 8; q++) acc[q] = 0.f;
        const uint4* x4 = reinterpret_cast<const uint4*>(bh + (size_t)b * Tlen * Idim);
        for (int t = g; t < Tlen; t += 4) {
            float a = s_al[t];
            uint4 v = x4[t * 64 + l];
            const __half2* hx = reinterpret_cast<const __half2*>(&v);
#pragma unroll
            for (int q = 0; q < 4; q++) {
                float2 f = __half22float2(hx[q]);
                acc[2*q]     += a * f.x;
                acc[2*q + 1] += a * f.y;
            }
        }
#pragma unroll
        for (int q = 0; q < 8; q++) s_ctx[g][l * 8 + q] = acc[q];
    }
    __syncthreads();

    // reduce groups + split-store ctx (2 cols per thread)
    {
        int c0 = tid * 2;
        float v0 = s_ctx[0][c0] + s_ctx[1][c0] + s_ctx[2][c0] + s_ctx[3][c0];
        float v1 = s_ctx[0][c0+1] + s_ctx[1][c0+1] + s_ctx[2][c0+1] + s_ctx[3][c0+1];
        __nv_bfloat16 h0, l0, h1, l1;
        split1(v0, &h0, &l0);
        split1(v1, &h1, &l1);
        reinterpret_cast<__nv_bfloat162*>(xhHi + (size_t)b * 1024)[tid] = __nv_bfloat162(h0, h1);
        reinterpret_cast<__nv_bfloat162*>(xhLo + (size_t)b * 1024)[tid] = __nv_bfloat162(l0, l1);
    }
}

// ---------------- smem sizes per config ----------------
#define SM_128_128 (2 * 2 * (128 * KCP * 2 + 128 * KCP * 2))  // 81920
#define SM_128_64  (2 * 2 * (128 * KCP * 2 + 64 * KCP * 2))   // 61440
#define SM_64_64   (2 * 2 * (64 * KCP * 2 + 64 * KCP * 2))    // 40960

// =============================================================================
extern "C" void kernel_launch(void* const* d_in, const int* in_sizes, int n_in,
                              void* d_out, int out_size)
{
    const float* batch_H = (const float*)d_in[0];
    const int*   text    = (const int*)  d_in[1];
    const float* W_feat  = (const float*)d_in[2];
    const float* W_hid   = (const float*)d_in[3];
    const float* b_hid   = (const float*)d_in[4];
    const float* w_score = (const float*)d_in[5];
    const float* W_ih    = (const float*)d_in[6];
    const float* W_hh    = (const float*)d_in[7];
    const float* b_ih    = (const float*)d_in[8];
    const float* b_hh    = (const float*)d_in[9];
    const float* W_gen   = (const float*)d_in[10];
    const float* b_gen   = (const float*)d_in[11];
    float* out = (float*)d_out;

    __half *feat16, *bh16;
    __nv_bfloat16 *bhHi, *bhLo, *outhHi, *outhLo;
    __nv_bfloat16 *xhHi0, *xhLo0;
    __nv_bfloat16 *Wfhi, *Wflo, *Whhi, *Whlo, *Wghi, *Wglo;
    float *hp, *cc, *b2i, *Wembi;
    cudaGetSymbolAddress((void**)&feat16, g_feat16);
    cudaGetSymbolAddress((void**)&bh16,   g_bh16);
    cudaGetSymbolAddress((void**)&bhHi,   g_bhHi);
    cudaGetSymbolAddress((void**)&bhLo,   g_bhLo);
    cudaGetSymbolAddress((void**)&xhHi0,  g_xhHi);
    cudaGetSymbolAddress((void**)&xhLo0,  g_xhLo);
    cudaGetSymbolAddress((void**)&outhHi, g_outhHi);
    cudaGetSymbolAddress((void**)&outhLo, g_outhLo);
    cudaGetSymbolAddress((void**)&hp,     g_hp);
    cudaGetSymbolAddress((void**)&cc,     g_c);
    cudaGetSymbolAddress((void**)&b2i,    g_b2i);
    cudaGetSymbolAddress((void**)&Wembi,  g_Wembi);
    cudaGetSymbolAddress((void**)&Wfhi,   g_Wfhi);
    cudaGetSymbolAddress((void**)&Wflo,   g_Wflo);
    cudaGetSymbolAddress((void**)&Whhi,   g_Whhi);
    cudaGetSymbolAddress((void**)&Whlo,   g_Whlo);
    cudaGetSymbolAddress((void**)&Wghi,   g_Wghi);
    cudaGetSymbolAddress((void**)&Wglo,   g_Wglo);

    cudaFuncSetAttribute((const void*)gemm2<128, 128, 2, 1, 0, __half>,
                         cudaFuncAttributeMaxDynamicSharedMemorySize, SM_128_128);
    cudaFuncSetAttribute((const void*)gemm2<128, 128, 2, 2, 1, float>,
                         cudaFuncAttributeMaxDynamicSharedMemorySize, SM_128_128);
    cudaFuncSetAttribute((const void*)gemm2<64, 64, 4, 2, 1, float>,
                         cudaFuncAttributeMaxDynamicSharedMemorySize, SM_64_64);
    cudaFuncSetAttribute((const void*)gates_lstm_kernel,
                         cudaFuncAttributeMaxDynamicSharedMemorySize, SM_128_64);

    // PDL launch config
    cudaLaunchAttribute pdlAttr[1];
    pdlAttr[0].id = cudaLaunchAttributeProgrammaticStreamSerialization;
    pdlAttr[0].val.programmaticStreamSerializationAllowed = 1;
    auto mkcfg = [&](dim3 g, unsigned int b, size_t sm) {
        cudaLaunchConfig_t c = {};
        c.gridDim = g; c.blockDim = dim3(b, 1, 1);
        c.dynamicSmemBytes = sm;
        c.attrs = pdlAttr; c.numAttrs = 1; c.stream = 0;
        return c;
    };

    // one-time packs + init (single kernel)
    mega_pack_kernel<<<NB_TOTAL, 256>>>(batch_H, W_feat, W_hid, b_hid,
                                        W_ih, W_hh, b_ih, b_hh, W_gen);

    // feat16 = batch_H @ W_feat^T : M=65536, N=512, K=512 (wait-first PDL)
    {
        cudaLaunchConfig_t c = mkcfg(dim3(4, (Bsz * Tlen) / 128), 256, SM_128_128);
        cudaLaunchKernelEx(&c, gemm2<128, 128, 2, 1, 0, __half>,
                           (const __nv_bfloat16*)bhHi, (const __nv_bfloat16*)bhLo,
                           (int)Idim,
                           (const __nv_bfloat16*)Wfhi, (const __nv_bfloat16*)Wflo,
                           (int)Idim,
                           (__half*)feat16, (int)Hdim, (const float*)nullptr,
                           512, 512);
    }

    for (int s = 0; s < Snum; s++) {
        __nv_bfloat16* xhHiC = xhHi0 + (size_t)(s & 1) * Bsz * 1024;
        __nv_bfloat16* xhLoC = xhLo0 + (size_t)(s & 1) * Bsz * 1024;
        __nv_bfloat16* xhHiN = xhHi0 + (size_t)((s + 1) & 1) * Bsz * 1024;
        __nv_bfloat16* xhLoN = xhLo0 + (size_t)((s + 1) & 1) * Bsz * 1024;

        // attention: writes ctx into current buffer
        {
            cudaLaunchConfig_t c = mkcfg(dim3(Bsz), 256, 0);
            cudaLaunchKernelEx(&c, attn_kernel,
                               (const __half*)feat16, (const __half*)bh16,
                               (const float*)hp, (const float*)w_score,
                               xhHiC, xhLoC);
        }

        // gates GEMM + fused LSTM: 128 blocks (BM=128, BN=64)
        {
            cudaLaunchConfig_t c = mkcfg(dim3(2048 / 64, Bsz / 128), 256, SM_128_64);
            cudaLaunchKernelEx(&c, gates_lstm_kernel,
                               (const __nv_bfloat16*)xhHiC, (const __nv_bfloat16*)xhLoC,
                               xhHiN, xhLoN,
                               (const float*)b2i, (const float*)Wembi,
                               (const int*)text, s, cc, outhHi, outhLo);
        }

        // hp for next step: 64 blocks (skip for last step)
        if (s + 1 < Snum) {
            cudaLaunchConfig_t c = mkcfg(dim3(512 / 64, Bsz / 64), 256, SM_64_64);
            cudaLaunchKernelEx(&c, gemm2<64, 64, 4, 2, 1, float>,
                               (const __nv_bfloat16*)(xhHiN + 512),
                               (const __nv_bfloat16*)(xhLoN + 512),
                               1024,
                               (const __nv_bfloat16*)Whhi, (const __nv_bfloat16*)Whlo,
                               512,
                               (float*)hp, 512, (const float*)b_hid,
                               512, 512);
        }
    }

    // probs = out_h @ W_gen^T + b_gen : M=13312, N=97, K=512
    {
        cudaLaunchConfig_t c = mkcfg(dim3(1, (Bsz * Snum) / 128), 256, SM_128_128);
        cudaLaunchKernelEx(&c, gemm2<128, 128, 2, 2, 1, float>,
                           (const __nv_bfloat16*)outhHi, (const __nv_bfloat16*)outhLo,
                           (int)Hdim,
                           (const __nv_bfloat16*)Wghi, (const __nv_bfloat16*)Wglo,
                           512,
                           (float*)out, (int)Cnum, (const float*)b_gen,
                           (int)Cnum, 512);
    }
}

// round 13
// speedup vs baseline: 1.1761x; 1.1761x over previous
#include <cuda_runtime.h>
#include <cuda_bf16.h>
#include <cuda_fp16.h>
#include <cstdint>

#define Bsz  512
#define Tlen 128
#define Idim 512
#define Hdim 512
#define Cnum 97
#define Snum 26
#define ICdim 609
#define KC  32                      // K elements per stage
#define KCP 40                      // padded row (80 B) -> conflict-free LDSM

// ---------------- device scratch (allocation-free rule) ----------------
__device__ __align__(16) __half g_feat16[(size_t)Bsz * Tlen * Hdim];  // 64 MiB
__device__ __align__(16) __half g_bh16[(size_t)Bsz * Tlen * Idim];    // 64 MiB
__device__ __align__(16) __nv_bfloat16 g_bhHi[(size_t)Bsz * Tlen * Idim];
__device__ __align__(16) __nv_bfloat16 g_bhLo[(size_t)Bsz * Tlen * Idim];
__device__ __align__(16) __nv_bfloat16 g_xhHi[2][Bsz * 1024];  // ping-pong [ctx|h]
__device__ __align__(16) __nv_bfloat16 g_xhLo[2][Bsz * 1024];
__device__ __align__(16) __nv_bfloat16 g_outhHi[(size_t)Bsz * Snum * Hdim];
__device__ __align__(16) __nv_bfloat16 g_outhLo[(size_t)Bsz * Snum * Hdim];
__device__ __align__(16) float g_hp[Bsz * Hdim];
__device__ __align__(16) float g_c[Bsz * Hdim];
__device__ __align__(16) float g_b2i[2048];                 // interleaved bias
__device__ __align__(16) float g_Wembi[Cnum * 2048];        // interleaved emb
// pre-split bf16 weights (hi/lo), [N,K] row-major
__device__ __align__(16) __nv_bfloat16 g_W2hi[2048 * 1024]; // interleaved rows
__device__ __align__(16) __nv_bfloat16 g_W2lo[2048 * 1024];
__device__ __align__(16) __nv_bfloat16 g_Wfhi[512 * 512];
__device__ __align__(16) __nv_bfloat16 g_Wflo[512 * 512];
__device__ __align__(16) __nv_bfloat16 g_Whhi[512 * 512];
__device__ __align__(16) __nv_bfloat16 g_Whlo[512 * 512];
__device__ __align__(16) __nv_bfloat16 g_Wghi[Cnum * 512];
__device__ __align__(16) __nv_bfloat16 g_Wglo[Cnum * 512];

// ---------------- helpers ----------------
__device__ __forceinline__ void stC(float* p, float v)  { *p = v; }
__device__ __forceinline__ void stC(__half* p, float v) { *p = __float2half(v); }

__device__ __forceinline__ float tanh_fast(float x) {
    float y;
    asm("tanh.approx.f32 %0, %1;" : "=f"(y) : "f"(x));
    return y;
}

__device__ __forceinline__ void split1(float v, __nv_bfloat16* hi, __nv_bfloat16* lo) {
    __nv_bfloat16 h = __float2bfloat16(v);
    *hi = h;
    *lo = __float2bfloat16(v - __bfloat162float(h));
}

#define MMA_B16(d, a, b)                                                     \
    asm volatile(                                                            \
        "mma.sync.aligned.m16n8k16.row.col.f32.bf16.bf16.f32 "               \
        "{%0,%1,%2,%3},{%4,%5,%6,%7},{%8,%9},{%0,%1,%2,%3};"                 \
        : "+f"((d)[0]), "+f"((d)[1]), "+f"((d)[2]), "+f"((d)[3])             \
        : "r"((a)[0]), "r"((a)[1]), "r"((a)[2]), "r"((a)[3]),                \
          "r"((b)[0]), "r"((b)[1]))

#define LDSM_X4(r, addr)                                                     \
    asm volatile("ldmatrix.sync.aligned.m8n8.x4.shared.b16 {%0,%1,%2,%3},[%4];" \
        : "=r"((r)[0]), "=r"((r)[1]), "=r"((r)[2]), "=r"((r)[3]) : "r"(addr))

#define CP16(dst, src, sz)                                                   \
    asm volatile("cp.async.cg.shared.global [%0], [%1], 16, %2;\n"           \
                 :: "r"(dst), "l"(src), "r"(sz))

// ====== templated pipeline: acc += A*B^T over K, double-buffered cp.async ====
// Block tile BM x BN, 256 threads, WR warp-rows x (8/WR) warp-cols.
// Per-output accumulation order identical for all configs (kc asc, k16 asc,
// hi*hi / hi*lo / lo*hi) -> bit-identical numerics across tilings.
template<int BM, int BN, int WR, int MT, int NT>
__device__ __forceinline__ void gemm_pipe(
    float (&acc)[MT][NT][4],
    const __nv_bfloat16* __restrict__ Ahi, const __nv_bfloat16* __restrict__ Alo,
    int lda,
    const __nv_bfloat16* __restrict__ Bhi, const __nv_bfloat16* __restrict__ Blo,
    int ldb, int N, int K, int m0, int n0, char* smem)
{
    constexpr int WC = 8 / WR;
    constexpr int ASTG = BM * KCP * 2;
    constexpr int BSTG = BN * KCP * 2;
    constexpr int STGT = 2 * (ASTG + BSTG);
    static_assert(MT == BM / (16 * WR) && NT == BN / (8 * WC), "tile mismatch");

    const uint32_t sbase = (uint32_t)__cvta_generic_to_shared(smem);
    const int tid = threadIdx.x, lane = tid & 31, warp = tid >> 5;
    const int wm = (warp / WC) * (MT * 16);
    const int wn = (warp % WC) * (NT * 8);

    const uint32_t aOff = (uint32_t)((wm + (lane & 15)) * (KCP * 2) + (lane >> 4) * 16);
    const uint32_t bOff = (uint32_t)((wn + ((lane >> 4) << 3) + (lane & 7)) * (KCP * 2)
                                     + ((lane >> 3) & 1) * 16);

    const __nv_bfloat16* asrc[2] = { Ahi, Alo };
    const __nv_bfloat16* bsrc[2] = { Bhi, Blo };

    auto prefetch = [&](int stg, int k0) {
        uint32_t st = sbase + (uint32_t)(stg * STGT);
        // A: BM rows x 4 16B-chunks, hi+lo
#pragma unroll
        for (int ch = tid; ch < BM * 4; ch += 256) {
            int row = ch >> 2, cc = ch & 3;
#pragma unroll
            for (int t = 0; t < 2; t++) {
                const void* sa = asrc[t] + (size_t)(m0 + row) * lda + k0 + cc * 8;
                uint32_t da = st + (uint32_t)(t * ASTG + row * (KCP * 2) + cc * 16);
                CP16(da, sa, 16);
            }
        }
        // B: BN rows x 4 chunks, hi+lo, N-guarded
#pragma unroll
        for (int ch = tid; ch < BN * 4; ch += 256) {
            int row = ch >> 2, cc = ch & 3;
            int gr = n0 + row;
            int rr = (gr < N) ? gr : 0;
            int sz = (gr < N) ? 16 : 0;
#pragma unroll
            for (int t = 0; t < 2; t++) {
                const void* sb = bsrc[t] + (size_t)rr * ldb + k0 + cc * 8;
                uint32_t db = st + (uint32_t)(2 * ASTG + t * BSTG + row * (KCP * 2) + cc * 16);
                CP16(db, sb, sz);
            }
        }
        asm volatile("cp.async.commit_group;\n");
    };

    const int nch = K / KC;
    prefetch(0, 0);

    for (int kc = 0; kc < nch; kc++) {
        if (kc + 1 < nch) {
            prefetch((kc + 1) & 1, (kc + 1) * KC);
            asm volatile("cp.async.wait_group 1;\n");
        } else {
            asm volatile("cp.async.wait_group 0;\n");
        }
        __syncthreads();

        uint32_t st = sbase + (uint32_t)((kc & 1) * STGT);
        uint32_t aB[2] = { st, st + ASTG };
        uint32_t bB[2] = { st + 2 * ASTG, st + 2 * ASTG + BSTG };

#pragma unroll
        for (int k16 = 0; k16 < 2; k16++) {
            uint32_t af[2][MT][4];
#pragma unroll
            for (int t = 0; t < 2; t++)
#pragma unroll
                for (int mt = 0; mt < MT; mt++) {
                    uint32_t ad = aB[t] + aOff + (uint32_t)(mt * 16 * KCP * 2 + k16 * 32);
                    LDSM_X4(af[t][mt], ad);
                }
#pragma unroll
            for (int p = 0; p < NT / 2; p++) {
                uint32_t bf[2][2][2];
#pragma unroll
                for (int t = 0; t < 2; t++) {
                    uint32_t bd = bB[t] + bOff + (uint32_t)(p * 16 * KCP * 2 + k16 * 32);
                    uint32_t r4[4];
                    LDSM_X4(r4, bd);
                    bf[t][0][0] = r4[0]; bf[t][0][1] = r4[1];
                    bf[t][1][0] = r4[2]; bf[t][1][1] = r4[3];
                }
#pragma unroll
                for (int mt = 0; mt < MT; mt++)
#pragma unroll
                    for (int q = 0; q < 2; q++) {
                        int nt = 2 * p + q;
                        MMA_B16(acc[mt][nt], af[0][mt], bf[0][q]);  // hi*hi
                        MMA_B16(acc[mt][nt], af[0][mt], bf[1][q]);  // hi*lo
                        MMA_B16(acc[mt][nt], af[1][mt], bf[0][q]);  // lo*hi
                    }
            }
        }
        __syncthreads();
    }
}

// ---------------- generic GEMM kernel (feat / hp / final) ----------------
template<int BM, int BN, int WR, int BIAS, typename OutT>
__global__ void __launch_bounds__(256, 2) gemm2(
    const __nv_bfloat16* __restrict__ Ahi, const __nv_bfloat16* __restrict__ Alo,
    int lda,
    const __nv_bfloat16* __restrict__ Bhi, const __nv_bfloat16* __restrict__ Blo,
    int ldb,
    OutT* __restrict__ C, int ldc, const float* __restrict__ bias,
    int N, int K)
{
    extern __shared__ __align__(16) char smem[];
    constexpr int WC = 8 / WR;
    constexpr int MT = BM / (16 * WR);
    constexpr int NT = BN / (8 * WC);
    const int m0 = blockIdx.y * BM, n0 = blockIdx.x * BN;
    const int lane = threadIdx.x & 31, warp = threadIdx.x >> 5;
    const int wm = (warp / WC) * (MT * 16);
    const int wn = (warp % WC) * (NT * 8);

    float acc[MT][NT][4];
#pragma unroll
    for (int i = 0; i < MT; i++)
#pragma unroll
        for (int j = 0; j < NT; j++)
#pragma unroll
            for (int r = 0; r < 4; r++) acc[i][j][r] = 0.f;

    gemm_pipe<BM, BN, WR>(acc, Ahi, Alo, lda, Bhi, Blo, ldb, N, K, m0, n0, smem);

    const int gid = lane >> 2, tig = lane & 3;
#pragma unroll
    for (int mt = 0; mt < MT; mt++) {
        int r0 = m0 + wm + mt * 16 + gid;
#pragma unroll
        for (int nt = 0; nt < NT; nt++) {
            int col = n0 + wn + nt * 8 + 2 * tig;
            float b0 = 0.f, b1 = 0.f;
            if (BIAS) {
                if (col < N)     b0 = bias[col];
                if (col + 1 < N) b1 = bias[col + 1];
            }
            if (col < N) {
                stC(&C[(size_t)r0 * ldc + col],       acc[mt][nt][0] + b0);
                stC(&C[(size_t)(r0 + 8) * ldc + col], acc[mt][nt][2] + b0);
            }
            if (col + 1 < N) {
                stC(&C[(size_t)r0 * ldc + col + 1],       acc[mt][nt][1] + b1);
                stC(&C[(size_t)(r0 + 8) * ldc + col + 1], acc[mt][nt][3] + b1);
            }
        }
    }
}

// ---------------- fused gates GEMM + LSTM epilogue ----------------
// BM=128, BN=64, WR=4 -> warp tile 32x32, grid (32, 4) = 128 blocks.
__global__ void __launch_bounds__(256, 2) gates_lstm_kernel(
    const __nv_bfloat16* __restrict__ Ahi, const __nv_bfloat16* __restrict__ Alo,
    __nv_bfloat16* __restrict__ xhHiN, __nv_bfloat16* __restrict__ xhLoN,
    const float* __restrict__ b2i, const float* __restrict__ Wembi,
    const int* __restrict__ text, int s, float* __restrict__ c,
    __nv_bfloat16* __restrict__ outhHi, __nv_bfloat16* __restrict__ outhLo)
{
    extern __shared__ __align__(16) char smem[];
    constexpr int BM = 128, BN = 64, WR = 4, WC = 2;
    constexpr int MT = BM / (16 * WR);   // 2
    constexpr int NT = BN / (8 * WC);    // 4
    const int tid = threadIdx.x, lane = tid & 31, warp = tid >> 5;
    const int wm = (warp / WC) * (MT * 16);
    const int wn = (warp % WC) * (NT * 8);
    const int m0 = blockIdx.y * BM, n0 = blockIdx.x * BN, j0 = n0 >> 2;

    float acc[MT][NT][4];
#pragma unroll
    for (int i = 0; i < MT; i++)
#pragma unroll
        for (int j = 0; j < NT; j++)
#pragma unroll
            for (int r = 0; r < 4; r++) acc[i][j][r] = 0.f;

    gemm_pipe<BM, BN, WR>(acc, Ahi, Alo, 1024, g_W2hi, g_W2lo, 1024,
                          2048, 1024, m0, n0, smem);

    // dump acc to smem (raw gate pre-activations for this 128x64 region)
    float* sg = (float*)smem;
    const int gid = lane >> 2, tig = lane & 3;
#pragma unroll
    for (int mt = 0; mt < MT; mt++) {
        int rl = wm + mt * 16 + gid;
#pragma unroll
        for (int nt = 0; nt < NT; nt++) {
            int cl = wn + nt * 8 + 2 * tig;
            sg[rl * BN + cl]           = acc[mt][nt][0];
            sg[rl * BN + cl + 1]       = acc[mt][nt][1];
            sg[(rl + 8) * BN + cl]     = acc[mt][nt][2];
            sg[(rl + 8) * BN + cl + 1] = acc[mt][nt][3];
        }
    }
    __syncthreads();

    // LSTM for (128 batches x 16 j): 2048 tasks, 8 per thread
#pragma unroll
    for (int it = 0; it < 8; it++) {
        int idx = tid + it * 256;
        int bl = idx >> 4, jl = idx & 15;
        int b = m0 + bl, j = j0 + jl;
        int ch = text[b * Snum + s];
        float4 gv = *reinterpret_cast<float4*>(&sg[bl * BN + jl * 4]);
        float4 bs = *reinterpret_cast<const float4*>(&b2i[n0 + jl * 4]);
        float4 ev = *reinterpret_cast<const float4*>(&Wembi[(size_t)ch * 2048 + n0 + jl * 4]);
        float ig = gv.x + bs.x + ev.x;
        float fg = gv.y + bs.y + ev.y;
        float gg = gv.z + bs.z + ev.z;
        float og = gv.w + bs.w + ev.w;
        float si = 1.f / (1.f + __expf(-ig));
        float sf = 1.f / (1.f + __expf(-fg));
        float so = 1.f / (1.f + __expf(-og));
        float c2v = sf * c[b * 512 + j] + si * tanhf(gg);
        float h2 = so * tanhf(c2v);
        c[b * 512 + j] = c2v;
        __nv_bfloat16 hh, hl;
        split1(h2, &hh, &hl);
        xhHiN[(size_t)b * 1024 + 512 + j] = hh;
        xhLoN[(size_t)b * 1024 + 512 + j] = hl;
        size_t oi = ((size_t)b * Snum + s) * 512 + j;
        outhHi[oi] = hh;
        outhLo[oi] = hl;
    }
}

// ---------------- mega pack: all one-time packs + init in ONE kernel ---------
#define NB_BH   32768   // (B*T*I/4)/256
#define NB_W2   8192    // 2048*1024/256
#define NB_WF   1024
#define NB_WH   1024
#define NB_WG   194
#define NB_EMB  776
#define NB_INIT 2048
#define NB_TOTAL (NB_BH + NB_W2 + NB_WF + NB_WH + NB_WG + NB_EMB + NB_INIT)

__global__ void __launch_bounds__(256) mega_pack_kernel(
    const float* __restrict__ bh, const float* __restrict__ W_feat,
    const float* __restrict__ W_hid, const float* __restrict__ b_hid,
    const float* __restrict__ W_ih, const float* __restrict__ W_hh,
    const float* __restrict__ b_ih, const float* __restrict__ b_hh,
    const float* __restrict__ W_gen)
{
    int bid = blockIdx.x, tid = threadIdx.x;

    if (bid < NB_BH) {        // batch_H -> fp16 + bf16 hi/lo
        int i = bid * 256 + tid;
        float4 v = reinterpret_cast<const float4*>(bh)[i];
        reinterpret_cast<__half2*>(g_bh16)[2 * i]     = __floats2half2_rn(v.x, v.y);
        reinterpret_cast<__half2*>(g_bh16)[2 * i + 1] = __floats2half2_rn(v.z, v.w);
        __nv_bfloat16 h0, l0, h1, l1, h2, l2, h3, l3;
        split1(v.x, &h0, &l0); split1(v.y, &h1, &l1);
        split1(v.z, &h2, &l2); split1(v.w, &h3, &l3);
        __nv_bfloat162* ph = reinterpret_cast<__nv_bfloat162*>(g_bhHi);
        __nv_bfloat162* pl = reinterpret_cast<__nv_bfloat162*>(g_bhLo);
        ph[2 * i]     = __nv_bfloat162(h0, h1);
        ph[2 * i + 1] = __nv_bfloat162(h2, h3);
        pl[2 * i]     = __nv_bfloat162(l0, l1);
        pl[2 * i + 1] = __nv_bfloat162(l2, l3);
        return;
    }
    bid -= NB_BH;
    if (bid < NB_W2) {        // W2 interleaved split + bias
        int i = bid * 256 + tid;
        int n = i >> 10, k = i & 1023;
        int r = (n & 3) * 512 + (n >> 2);
        float v = (k < 512) ? W_ih[(size_t)r * ICdim + k]
                            : W_hh[(size_t)r * 512 + (k - 512)];
        split1(v, &g_W2hi[i], &g_W2lo[i]);
        if (i < 2048) {
            int rr = (i & 3) * 512 + (i >> 2);
            g_b2i[i] = b_ih[rr] + b_hh[rr];
        }
        return;
    }
    bid -= NB_W2;
    if (bid < NB_WF) {        // W_feat split
        int i = bid * 256 + tid;
        split1(W_feat[i], &g_Wfhi[i], &g_Wflo[i]);
        return;
    }
    bid -= NB_WF;
    if (bid < NB_WH) {        // W_hid split
        int i = bid * 256 + tid;
        split1(W_hid[i], &g_Whhi[i], &g_Whlo[i]);
        return;
    }
    bid -= NB_WH;
    if (bid < NB_WG) {        // W_gen split
        int i = bid * 256 + tid;
        if (i < Cnum * 512) split1(W_gen[i], &g_Wghi[i], &g_Wglo[i]);
        return;
    }
    bid -= NB_WG;
    if (bid < NB_EMB) {       // onehot embedding (interleaved)
        int i = bid * 256 + tid;
        if (i < Cnum * 2048) {
            int cc = i >> 11, n = i & 2047;
            int r = (n & 3) * 512 + (n >> 2);
            g_Wembi[i] = W_ih[(size_t)r * ICdim + 512 + cc];
        }
        return;
    }
    bid -= NB_EMB;
    {                          // init xh / c / hp0
        int i = bid * 256 + tid;
        __nv_bfloat16 z = __float2bfloat16(0.f);
        g_xhHi[0][i] = z; g_xhLo[0][i] = z;
        g_xhHi[1][i] = z; g_xhLo[1][i] = z;
        if (i < Bsz * Hdim) {
            g_c[i] = 0.f;
            g_hp[i] = b_hid[i & 511];         // h0 = 0 -> hp0 = b_hid
        }
    }
}

// ---------------- fused attention: e -> softmax -> ctx -----------------------
__global__ void __launch_bounds__(256) attn_kernel(
    const __half* __restrict__ feat,
    const __half* __restrict__ bh,
    const float* __restrict__ hp,
    const float* __restrict__ wsc,
    __nv_bfloat16* __restrict__ xhHi, __nv_bfloat16* __restrict__ xhLo)
{
    int b = blockIdx.x, tid = threadIdx.x;
    int warp = tid >> 5, lane = tid & 31;
    __shared__ float s_al[Tlen];
    __shared__ float s_red[8];
    __shared__ float s_ctx[4][512];

    // preload hp/w chunks owned by this lane (cols lane*8..+8 and +256)
    float hpr[16], wr[16];
    {
        const float* hpb = hp + (size_t)b * 512;
#pragma unroll
        for (int j = 0; j < 2; j++) {
            float4 a0 = *reinterpret_cast<const float4*>(hpb + j * 256 + lane * 8);
            float4 a1 = *reinterpret_cast<const float4*>(hpb + j * 256 + lane * 8 + 4);
            float4 w0 = *reinterpret_cast<const float4*>(wsc + j * 256 + lane * 8);
            float4 w1 = *reinterpret_cast<const float4*>(wsc + j * 256 + lane * 8 + 4);
            hpr[j*8+0]=a0.x; hpr[j*8+1]=a0.y; hpr[j*8+2]=a0.z; hpr[j*8+3]=a0.w;
            hpr[j*8+4]=a1.x; hpr[j*8+5]=a1.y; hpr[j*8+6]=a1.z; hpr[j*8+7]=a1.w;
            wr[j*8+0]=w0.x;  wr[j*8+1]=w0.y;  wr[j*8+2]=w0.z;  wr[j*8+3]=w0.w;
            wr[j*8+4]=w1.x;  wr[j*8+5]=w1.y;  wr[j*8+6]=w1.z;  wr[j*8+7]=w1.w;
        }
    }

    // e-pass: warp per t, 16 t per warp, 16B feat loads
    for (int t = warp; t < Tlen; t += 8) {
        const uint4* f4 = reinterpret_cast<const uint4*>(
            feat + ((size_t)b * Tlen + t) * Hdim);
        float s = 0.f;
#pragma unroll
        for (int j = 0; j < 2; j++) {
            uint4 v = f4[lane + 32 * j];
            const __half2* hx = reinterpret_cast<const __half2*>(&v);
#pragma unroll
            for (int q = 0; q < 4; q++) {
                float2 f = __half22float2(hx[q]);
                s += tanh_fast(f.x + hpr[j*8 + 2*q])     * wr[j*8 + 2*q]
                   + tanh_fast(f.y + hpr[j*8 + 2*q + 1]) * wr[j*8 + 2*q + 1];
            }
        }
#pragma unroll
        for (int o = 16; o; o >>= 1) s += __shfl_down_sync(0xffffffffu, s, o);
        if (lane == 0) s_al[t] = s;
    }
    __syncthreads();

    // softmax (threads 0..127)
    if (tid < Tlen) {
        float v = s_al[tid];
        float m = v;
#pragma unroll
        for (int o = 16; o; o >>= 1) m = fmaxf(m, __shfl_xor_sync(0xffffffffu, m, o));
        if (lane == 0) s_red[warp] = m;
    }
    __syncthreads();
    if (tid < Tlen) {
        float m = fmaxf(fmaxf(s_red[0], s_red[1]), fmaxf(s_red[2], s_red[3]));
        float ex = __expf(s_al[tid] - m);
        float ss = ex;
#pragma unroll
        for (int o = 16; o; o >>= 1) ss += __shfl_xor_sync(0xffffffffu, ss, o);
        if (lane == 0) s_red[4 + warp] = ss;
        s_al[tid] = ex;
    }
    __syncthreads();
    if (tid < Tlen) {
        float inv = 1.f / (s_red[4] + s_red[5] + s_red[6] + s_red[7]);
        s_al[tid] *= inv;
    }
    __syncthreads();

    // ctx-pass: 4 T-groups x 64 threads; each thread owns 8 cols, 16B loads
    {
        int g = tid >> 6, l = tid & 63;
        float acc[8];
#pragma unroll
        for (int q = 0; q < 8; q++) acc[q] = 0.f;
        const uint4* x4 = reinterpret_cast<const uint4*>(bh + (size_t)b * Tlen * Idim);
        for (int t = g; t < Tlen; t += 4) {
            float a = s_al[t];
            uint4 v = x4[t * 64 + l];
            const __half2* hx = reinterpret_cast<const __half2*>(&v);
#pragma unroll
            for (int q = 0; q < 4; q++) {
                float2 f = __half22float2(hx[q]);
                acc[2*q]     += a * f.x;
                acc[2*q + 1] += a * f.y;
            }
        }
#pragma unroll
        for (int q = 0; q < 8; q++) s_ctx[g][l * 8 + q] = acc[q];
    }
    __syncthreads();

    // reduce groups + split-store ctx (2 cols per thread)
    {
        int c0 = tid * 2;
        float v0 = s_ctx[0][c0] + s_ctx[1][c0] + s_ctx[2][c0] + s_ctx[3][c0];
        float v1 = s_ctx[0][c0+1] + s_ctx[1][c0+1] + s_ctx[2][c0+1] + s_ctx[3][c0+1];
        __nv_bfloat16 h0, l0, h1, l1;
        split1(v0, &h0, &l0);
        split1(v1, &h1, &l1);
        reinterpret_cast<__nv_bfloat162*>(xhHi + (size_t)b * 1024)[tid] = __nv_bfloat162(h0, h1);
        reinterpret_cast<__nv_bfloat162*>(xhLo + (size_t)b * 1024)[tid] = __nv_bfloat162(l0, l1);
    }
}

// ---------------- smem sizes per config ----------------
#define SM_128_128 (2 * 2 * (128 * KCP * 2 + 128 * KCP * 2))  // 81920
#define SM_128_64  (2 * 2 * (128 * KCP * 2 + 64 * KCP * 2))   // 61440
#define SM_64_32   (2 * 2 * (64 * KCP * 2 + 32 * KCP * 2))    // 30720

// =============================================================================
extern "C" void kernel_launch(void* const* d_in, const int* in_sizes, int n_in,
                              void* d_out, int out_size)
{
    const float* batch_H = (const float*)d_in[0];
    const int*   text    = (const int*)  d_in[1];
    const float* W_feat  = (const float*)d_in[2];
    const float* W_hid   = (const float*)d_in[3];
    const float* b_hid   = (const float*)d_in[4];
    const float* w_score = (const float*)d_in[5];
    const float* W_ih    = (const float*)d_in[6];
    const float* W_hh    = (const float*)d_in[7];
    const float* b_ih    = (const float*)d_in[8];
    const float* b_hh    = (const float*)d_in[9];
    const float* W_gen   = (const float*)d_in[10];
    const float* b_gen   = (const float*)d_in[11];
    float* out = (float*)d_out;

    __half *feat16, *bh16;
    __nv_bfloat16 *bhHi, *bhLo, *outhHi, *outhLo;
    __nv_bfloat16 *xhHi0, *xhLo0;
    __nv_bfloat16 *Wfhi, *Wflo, *Whhi, *Whlo, *Wghi, *Wglo;
    float *hp, *cc, *b2i, *Wembi;
    cudaGetSymbolAddress((void**)&feat16, g_feat16);
    cudaGetSymbolAddress((void**)&bh16,   g_bh16);
    cudaGetSymbolAddress((void**)&bhHi,   g_bhHi);
    cudaGetSymbolAddress((void**)&bhLo,   g_bhLo);
    cudaGetSymbolAddress((void**)&xhHi0,  g_xhHi);
    cudaGetSymbolAddress((void**)&xhLo0,  g_xhLo);
    cudaGetSymbolAddress((void**)&outhHi, g_outhHi);
    cudaGetSymbolAddress((void**)&outhLo, g_outhLo);
    cudaGetSymbolAddress((void**)&hp,     g_hp);
    cudaGetSymbolAddress((void**)&cc,     g_c);
    cudaGetSymbolAddress((void**)&b2i,    g_b2i);
    cudaGetSymbolAddress((void**)&Wembi,  g_Wembi);
    cudaGetSymbolAddress((void**)&Wfhi,   g_Wfhi);
    cudaGetSymbolAddress((void**)&Wflo,   g_Wflo);
    cudaGetSymbolAddress((void**)&Whhi,   g_Whhi);
    cudaGetSymbolAddress((void**)&Whlo,   g_Whlo);
    cudaGetSymbolAddress((void**)&Wghi,   g_Wghi);
    cudaGetSymbolAddress((void**)&Wglo,   g_Wglo);

    cudaFuncSetAttribute((const void*)gemm2<128, 128, 2, 0, __half>,
                         cudaFuncAttributeMaxDynamicSharedMemorySize, SM_128_128);
    cudaFuncSetAttribute((const void*)gemm2<128, 128, 2, 1, float>,
                         cudaFuncAttributeMaxDynamicSharedMemorySize, SM_128_128);
    cudaFuncSetAttribute((const void*)gemm2<64, 32, 4, 1, float>,
                         cudaFuncAttributeMaxDynamicSharedMemorySize, SM_64_32);
    cudaFuncSetAttribute((const void*)gates_lstm_kernel,
                         cudaFuncAttributeMaxDynamicSharedMemorySize, SM_128_64);

    // one-time packs + init (single kernel)
    mega_pack_kernel<<<NB_TOTAL, 256>>>(batch_H, W_feat, W_hid, b_hid,
                                        W_ih, W_hh, b_ih, b_hh, W_gen);

    // feat16 = batch_H @ W_feat^T : M=65536, N=512, K=512
    gemm2<128, 128, 2, 0, __half><<<dim3(4, (Bsz * Tlen) / 128), 256, SM_128_128>>>(
        bhHi, bhLo, Idim, Wfhi, Wflo, Idim, feat16, Hdim, nullptr, 512, 512);

    for (int s = 0; s < Snum; s++) {
        __nv_bfloat16* xhHiC = xhHi0 + (size_t)(s & 1) * Bsz * 1024;
        __nv_bfloat16* xhLoC = xhLo0 + (size_t)(s & 1) * Bsz * 1024;
        __nv_bfloat16* xhHiN = xhHi0 + (size_t)((s + 1) & 1) * Bsz * 1024;
        __nv_bfloat16* xhLoN = xhLo0 + (size_t)((s + 1) & 1) * Bsz * 1024;

        // attention: writes ctx into current buffer
        attn_kernel<<<Bsz, 256>>>(feat16, bh16, hp, w_score, xhHiC, xhLoC);

        // gates GEMM + fused LSTM: 128 blocks (BM=128, BN=64)
        gates_lstm_kernel<<<dim3(2048 / 64, Bsz / 128), 256, SM_128_64>>>(
            xhHiC, xhLoC, xhHiN, xhLoN, b2i, Wembi, text, s, cc,
            outhHi, outhLo);

        // hp for next step: 128 blocks (BM=64, BN=32), skip dead last one
        if (s + 1 < Snum) {
            gemm2<64, 32, 4, 1, float><<<dim3(512 / 32, Bsz / 64), 256, SM_64_32>>>(
                xhHiN + 512, xhLoN + 512, 1024, Whhi, Whlo, 512,
                hp, 512, b_hid, 512, 512);
        }
    }

    // probs = out_h @ W_gen^T + b_gen : M=13312, N=97, K=512
    gemm2<128, 128, 2, 1, float><<<dim3(1, (Bsz * Snum) / 128), 256, SM_128_128>>>(
        outhHi, outhLo, Hdim, Wghi, Wglo, 512, out, Cnum, b_gen, Cnum, 512);
}